// round 3
// baseline (speedup 1.0000x reference)
#include <cuda_runtime.h>

#define N_B 8
#define A_N 131072
#define T_N 64
#define CAND 4096
#define NEG_TCUT 0.02f
typedef unsigned long long ull;

// Scratch (static __device__ — no allocations allowed)
__device__ ull           g_gt_best[N_B * T_N];     // packed (iou_bits<<32 | ~anchor)
__device__ float         g_iou_max[N_B * A_N];
__device__ unsigned char g_best_g [N_B * A_N];
__device__ unsigned char g_isbest [N_B * A_N];
__device__ signed char   g_cls0  [N_B * A_N];
__device__ ull           g_thresh[N_B * 2];        // [pos_th, neg_th] per batch
__device__ int           g_tot   [N_B * 2];        // total pos / neg counts
__device__ int           g_ccnt  [N_B * 2];        // candidate counts
__device__ ull           g_cand  [N_B * 2 * CAND];
__device__ int           g_fb    [N_B * 2];        // fallback rank k (0 = none)

__global__ void k_init() {
    const int i = blockIdx.x * blockDim.x + threadIdx.x;
    // clear isbest (1MB) with int4 stores: 65536 int4 slots
    if (i < (N_B * A_N) / 16)
        reinterpret_cast<int4*>(g_isbest)[i] = make_int4(0, 0, 0, 0);
    if (i < N_B * T_N) g_gt_best[i] = 0xFFFFFFFFull;  // (iou=0, anchor 0) seed
    if (i < N_B * 2) { g_tot[i] = 0; g_ccnt[i] = 0; g_fb[i] = 0; }
}

__global__ void k_iou(const float4* __restrict__ anchors, const float4* __restrict__ gts) {
    const int b   = blockIdx.y;
    const int a   = blockIdx.x * blockDim.x + threadIdx.x;
    const int tid = threadIdx.x;

    __shared__ float4   sgt [T_N];
    __shared__ float    sga [T_N];
    __shared__ unsigned sflt[T_N];   // iou bits running max (filter)
    __shared__ ull      skey[T_N];   // packed best key

    if (tid < T_N) {
        float4 g = gts[b * T_N + tid];
        sgt[tid] = g;
        sga[tid] = (g.z - g.x) * (g.w - g.y);
        sflt[tid] = 1u;              // smallest positive float bits: iou must be > 0 to pass
        skey[tid] = 0ull;
    }
    __syncthreads();

    float4 box = anchors[b * A_N + a];
    bool inb = (box.x >= 0.f) && (box.y >= 0.f) && (box.z <= 1.f) && (box.w <= 1.f);
    if (!inb) { box.x = box.y = box.z = box.w = 0.f; }
    const float aarea = (box.z - box.x) * (box.w - box.y);

    float mymax = 0.f;   // iou >= 0 always; strict > keeps first-max (matches jnp.argmax)
    int   myg   = 0;
    ull   mask  = 0ull;

    #pragma unroll
    for (int g = 0; g < T_N; ++g) {
        float4 G = sgt[g];
        float ih = fmaxf(fminf(box.z, G.z) - fmaxf(box.x, G.x), 0.f);
        float iw = fmaxf(fminf(box.w, G.w) - fmaxf(box.y, G.y), 0.f);
        float inter = ih * iw;
        float un = (aarea + sga[g]) - inter;        // > 0 whenever inter > 0
        float q  = __fdiv_rn(inter, un);            // branchless; NaN selected away
        float iou = (inter > 0.f) ? q : 0.f;
        if (iou > mymax) { mymax = iou; myg = g; }
        if (__float_as_uint(iou) >= sflt[g]) mask |= (1ull << g);
    }

    g_iou_max[b * A_N + a] = mymax;
    g_best_g [b * A_N + a] = (unsigned char)myg;

    // slow path: ~ln(block) expected passes per gt per block
    const unsigned ainv = 0xFFFFFFFFu - (unsigned)a;
    while (mask) {
        int g = __ffsll(mask) - 1;
        mask &= mask - 1;
        float4 G = sgt[g];
        float ih = fmaxf(fminf(box.z, G.z) - fmaxf(box.x, G.x), 0.f);
        float iw = fmaxf(fminf(box.w, G.w) - fmaxf(box.y, G.y), 0.f);
        float inter = ih * iw;
        float un = (aarea + sga[g]) - inter;
        float iou = (inter > 0.f) ? __fdiv_rn(inter, un) : 0.f;
        unsigned bits = __float_as_uint(iou);
        atomicMax(&sflt[g], bits);
        atomicMax(&skey[g], ((ull)bits << 32) | ainv);
    }

    __syncthreads();
    if (tid < T_N && skey[tid]) atomicMax(&g_gt_best[b * T_N + tid], skey[tid]);
}

__global__ void k_mark() {
    const int i = blockIdx.x * blockDim.x + threadIdx.x;   // (b*T_N + g)
    if (i < N_B * T_N) {
        const int b = i / T_N;
        unsigned a = 0xFFFFFFFFu - (unsigned)(g_gt_best[i] & 0xFFFFFFFFull);
        g_isbest[b * A_N + a] = 1;
    }
}

// warp-aggregated candidate push (all lanes must call)
__device__ __forceinline__ void push_cand(ull* __restrict__ buf, int* __restrict__ cnt,
                                          ull key, bool p) {
    unsigned m = __ballot_sync(0xFFFFFFFFu, p);
    if (!m) return;
    int lane = threadIdx.x & 31;
    int leader = __ffs(m) - 1;
    int base = 0;
    if (lane == leader) base = atomicAdd(cnt, __popc(m));
    base = __shfl_sync(0xFFFFFFFFu, base, leader);
    if (p) {
        int slot = base + __popc(m & ((1u << lane) - 1));
        if (slot < CAND) buf[slot] = key;
    }
}

__global__ void k_cls(const float* __restrict__ rpos, const float* __restrict__ rneg) {
    const int b = blockIdx.y;
    const int a = blockIdx.x * blockDim.x + threadIdx.x;
    const int i = b * A_N + a;

    __shared__ int sc[2];
    if (threadIdx.x < 2) sc[threadIdx.x] = 0;
    __syncthreads();

    float im = g_iou_max[i];
    int cls = -1;
    if (im < 0.3f) cls = 0;
    if (g_isbest[i] || im >= 0.7f) cls = 1;
    g_cls0[i] = (signed char)cls;

    const bool pos = (cls == 1);
    const bool neg = (cls == 0);

    // block counts via ballot
    unsigned mp = __ballot_sync(0xFFFFFFFFu, pos);
    unsigned mn = __ballot_sync(0xFFFFFFFFu, neg);
    if ((threadIdx.x & 31) == 0) {
        if (mp) atomicAdd(&sc[0], __popc(mp));
        if (mn) atomicAdd(&sc[1], __popc(mn));
    }

    // candidates
    float rp = pos ? rpos[i] : 0.f;
    push_cand(g_cand + (b * 2 + 0) * CAND, &g_ccnt[b * 2 + 0],
              ((ull)__float_as_uint(rp) << 32) | (unsigned)a, pos);
    float rn = neg ? rneg[i] : 1.f;
    push_cand(g_cand + (b * 2 + 1) * CAND, &g_ccnt[b * 2 + 1],
              ((ull)__float_as_uint(rn) << 32) | (unsigned)a, neg && (rn < NEG_TCUT));

    __syncthreads();
    if (threadIdx.x < 2 && sc[threadIdx.x]) atomicAdd(&g_tot[b * 2 + threadIdx.x], sc[threadIdx.x]);
}

__global__ void k_pick() {
    const int b = blockIdx.x;
    const int tid = threadIdx.x;
    __shared__ ull sk[CAND];

    const int P  = g_tot[b * 2 + 0];
    const int cp = g_ccnt[b * 2 + 0];
    const int Nn = g_tot[b * 2 + 1];
    const int cn = g_ccnt[b * 2 + 1];
    const int npos = (P < 128) ? P : 128;
    const int Kn = 256 - npos;

    // ---- positives: K = 128, candidates = all positives (complete iff cp <= CAND) ----
    if (P <= 128) {
        if (tid == 0) g_thresh[b * 2 + 0] = ~0ull;
    } else if (cp <= CAND) {
        for (int i = tid; i < cp; i += blockDim.x) sk[i] = g_cand[(b * 2 + 0) * CAND + i];
        __syncthreads();
        for (int i = tid; i < cp; i += blockDim.x) {
            ull me = sk[i];
            int c = 0;
            for (int j = 0; j < cp; ++j) c += (sk[j] < me);
            if (c == 127) g_thresh[b * 2 + 0] = me;
        }
        __syncthreads();
    } else {
        if (tid == 0) g_fb[b * 2 + 0] = 128;
    }

    // ---- negatives: K = Kn, candidates = neg with r < NEG_TCUT ----
    if (Nn <= Kn) {
        if (tid == 0) g_thresh[b * 2 + 1] = ~0ull;
    } else if (cn >= Kn && cn <= CAND) {
        __syncthreads();
        for (int i = tid; i < cn; i += blockDim.x) sk[i] = g_cand[(b * 2 + 1) * CAND + i];
        __syncthreads();
        for (int i = tid; i < cn; i += blockDim.x) {
            ull me = sk[i];
            int c = 0;
            for (int j = 0; j < cn; ++j) c += (sk[j] < me);
            if (c == Kn - 1) g_thresh[b * 2 + 1] = me;
        }
    } else {
        if (tid == 0) g_fb[b * 2 + 1] = Kn;
    }
}

// ---- fallback exact radix select (normally early-exits) ----
__device__ __forceinline__ ull radix_select(const float* __restrict__ r,
                                            const signed char* __restrict__ cls,
                                            int want, int k, int* hist, int* sh) {
    ull prefix = 0;
    const int tid = threadIdx.x;
    for (int byte = 7; byte >= 0; --byte) {
        const int shift = byte * 8;
        if (tid < 256) hist[tid] = 0;
        __syncthreads();
        for (int i = tid; i < A_N; i += blockDim.x) {
            if (cls[i] == want) {
                ull key = ((ull)__float_as_uint(r[i]) << 32) | (unsigned)i;
                bool match = (byte == 7) || ((key >> (shift + 8)) == (prefix >> (shift + 8)));
                if (match) atomicAdd(&hist[(int)((key >> shift) & 0xFF)], 1);
            }
        }
        __syncthreads();
        if (tid == 0) {
            int cum = 0, d = 0;
            for (; d < 255; ++d) {
                if (cum + hist[d] >= k) break;
                cum += hist[d];
            }
            sh[0] = d;
            sh[1] = k - cum;
        }
        __syncthreads();
        prefix |= ((ull)sh[0]) << shift;
        k = sh[1];
        __syncthreads();
    }
    return prefix;
}

__global__ void k_fallback(const float* __restrict__ rpos, const float* __restrict__ rneg) {
    const int b = blockIdx.x;
    const int kp = g_fb[b * 2 + 0];
    const int kn = g_fb[b * 2 + 1];
    if (!(kp | kn)) return;
    __shared__ int hist[256];
    __shared__ int sh[2];
    if (kp) {
        ull t = radix_select(rpos + b * A_N, g_cls0 + b * A_N, 1, kp, hist, sh);
        if (threadIdx.x == 0) g_thresh[b * 2 + 0] = t;
    }
    if (kn) {
        ull t = radix_select(rneg + b * A_N, g_cls0 + b * A_N, 0, kn, hist, sh);
        if (threadIdx.x == 0) g_thresh[b * 2 + 1] = t;
    }
}

__global__ void k_out(const float4* __restrict__ anchors, const float4* __restrict__ gts,
                      const float* __restrict__ rpos, const float* __restrict__ rneg,
                      float* __restrict__ out) {
    const int b = blockIdx.y;
    const int a = blockIdx.x * blockDim.x + threadIdx.x;
    const int i = b * A_N + a;

    int cls = g_cls0[i];
    if (cls == 1) {
        ull key = ((ull)__float_as_uint(rpos[i]) << 32) | (unsigned)a;
        if (key > g_thresh[b * 2]) cls = -1;
    } else if (cls == 0) {
        ull key = ((ull)__float_as_uint(rneg[i]) << 32) | (unsigned)a;
        if (key > g_thresh[b * 2 + 1]) cls = -1;
    }
    out[i] = (float)cls;

    float4 d = make_float4(0.f, 0.f, 0.f, 0.f);
    if (cls == 1) {
        float4 box = anchors[i];
        bool inb = (box.x >= 0.f) && (box.y >= 0.f) && (box.z <= 1.f) && (box.w <= 1.f);
        if (!inb) { box.x = box.y = box.z = box.w = 0.f; }
        float4 gt = gts[b * T_N + g_best_g[i]];
        float ah = box.z - box.x, aw = box.w - box.y;
        float acy = box.x + 0.5f * ah, acx = box.y + 0.5f * aw;
        float gh = gt.z - gt.x, gw = gt.w - gt.y;
        float gcy = gt.x + 0.5f * gh, gcx = gt.y + 0.5f * gw;
        float ahs = (ah > 0.f) ? ah : 1.f;
        float aws = (aw > 0.f) ? aw : 1.f;
        float ghs = (gh > 0.f) ? gh : 1.f;
        float gws = (gw > 0.f) ? gw : 1.f;
        d.x = __fdiv_rn(gcy - acy, ahs);
        d.y = __fdiv_rn(gcx - acx, aws);
        d.z = logf(__fdiv_rn(ghs, ahs));
        d.w = logf(__fdiv_rn(gws, aws));
    }
    reinterpret_cast<float4*>(out + (size_t)N_B * A_N)[i] = d;
}

extern "C" void kernel_launch(void* const* d_in, const int* in_sizes, int n_in,
                              void* d_out, int out_size) {
    const float4* anchors = (const float4*)d_in[0];
    const float4* gts     = (const float4*)d_in[1];
    const float*  rp      = (const float*)d_in[2];
    const float*  rn      = (const float*)d_in[3];
    float* out = (float*)d_out;

    dim3 grid(A_N / 256, N_B);
    k_init<<<(N_B * A_N / 16 + 255) / 256, 256>>>();
    k_iou<<<grid, 256>>>(anchors, gts);
    k_mark<<<1, 512>>>();
    k_cls<<<grid, 256>>>(rp, rn);
    k_pick<<<N_B, 1024>>>();
    k_fallback<<<N_B, 1024>>>(rp, rn);
    k_out<<<grid, 256>>>(anchors, gts, rp, rn, out);
}

// round 4
// speedup vs baseline: 1.0720x; 1.0720x over previous
#include <cuda_runtime.h>

#define N_B 8
#define A_N 131072
#define T_N 64
#define CAND 4096
#define NEG_TCUT 0.02f
#define APT 8                 // anchors per thread (register-blocked)
#define TPB 256
#define APB (APT * TPB)       // anchors per block = 2048
typedef unsigned long long ull;

// Scratch (static __device__ — no allocations allowed)
__device__ ull           g_gt_best[N_B * T_N];     // packed (iou_bits<<32 | ~anchor)
__device__ float         g_iou_max[N_B * A_N];
__device__ unsigned char g_best_g [N_B * A_N];
__device__ signed char   g_cls0  [N_B * A_N];
__device__ ull           g_thresh[N_B * 2];        // [pos_th, neg_th] per batch
__device__ int           g_tot   [N_B * 2];        // total pos / neg counts
__device__ int           g_ccnt  [N_B * 2];        // candidate counts
__device__ ull           g_cand  [N_B * 2 * CAND];
__device__ int           g_fb    [N_B * 2];        // fallback rank k (0 = none)

__global__ void k_init() {
    const int i = threadIdx.x;
    if (i < N_B * T_N) g_gt_best[i] = 0xFFFFFFFFull;  // seed: (iou=0, anchor 0)
    if (i < N_B * 2) { g_tot[i] = 0; g_ccnt[i] = 0; g_fb[i] = 0; }
}

__global__ __launch_bounds__(TPB) void k_iou(const float4* __restrict__ anchors,
                                             const float4* __restrict__ gts) {
    const int b   = blockIdx.y;
    const int tid = threadIdx.x;
    const int a0  = blockIdx.x * APB + tid;     // thread's anchors: a0 + k*TPB

    __shared__ float4 sgt [T_N];
    __shared__ float  sga [T_N];
    __shared__ ull    skey[T_N];

    if (tid < T_N) {
        float4 g = gts[b * T_N + tid];
        sgt[tid] = g;
        sga[tid] = (g.z - g.x) * (g.w - g.y);
        skey[tid] = 0ull;
    }
    __syncthreads();

    // load 8 anchors into registers
    float4 box[APT];
    float  aarea[APT];
    float  bmax[APT];
    int    bg[APT];
    #pragma unroll
    for (int k = 0; k < APT; ++k) {
        float4 x = anchors[b * A_N + a0 + k * TPB];
        bool inb = (x.x >= 0.f) && (x.y >= 0.f) && (x.z <= 1.f) && (x.w <= 1.f);
        if (!inb) { x.x = x.y = x.z = x.w = 0.f; }
        box[k]   = x;
        aarea[k] = (x.z - x.x) * (x.w - x.y);
        bmax[k]  = 0.f;
        bg[k]    = 0;
    }

    #pragma unroll 1
    for (int g = 0; g < T_N; ++g) {
        const float4 G  = sgt[g];                 // broadcast LDS, serves 8*32 pairs
        const float  ga = sga[g];
        unsigned gb_bits = 0u;                    // thread-local best for this gt
        unsigned gb_a    = 0u;

        #pragma unroll
        for (int k = 0; k < APT; ++k) {
            float ih = fmaxf(fminf(box[k].z, G.z) - fmaxf(box[k].x, G.x), 0.f);
            float iw = fmaxf(fminf(box[k].w, G.w) - fmaxf(box[k].y, G.y), 0.f);
            float inter = ih * iw;
            float un = (aarea[k] + ga) - inter;   // > 0 whenever inter > 0
            float q  = __fdiv_rn(inter, un);      // IEEE rn: matches XLA exactly
            float iou = (inter > 0.f) ? q : 0.f;
            if (iou > bmax[k]) { bmax[k] = iou; bg[k] = g; }   // first-max over g
            unsigned bits = __float_as_uint(iou);
            if (bits > gb_bits) { gb_bits = bits; gb_a = (unsigned)(a0 + k * TPB); }
        }                                          // k ascending => smallest anchor on ties

        if (gb_bits) {
            ull key = ((ull)gb_bits << 32) | (0xFFFFFFFFu - gb_a);
            if (key > skey[g]) atomicMax(&skey[g], key);       // read-filter, rare ATOMS
        }
    }

    #pragma unroll
    for (int k = 0; k < APT; ++k) {
        g_iou_max[b * A_N + a0 + k * TPB] = bmax[k];
        g_best_g [b * A_N + a0 + k * TPB] = (unsigned char)bg[k];
    }

    __syncthreads();
    if (tid < T_N && skey[tid] > 0xFFFFFFFFull)
        atomicMax(&g_gt_best[b * T_N + tid], skey[tid]);
}

// warp-aggregated candidate push (all lanes must call)
__device__ __forceinline__ void push_cand(ull* __restrict__ buf, int* __restrict__ cnt,
                                          ull key, bool p) {
    unsigned m = __ballot_sync(0xFFFFFFFFu, p);
    if (!m) return;
    int lane = threadIdx.x & 31;
    int leader = __ffs(m) - 1;
    int base = 0;
    if (lane == leader) base = atomicAdd(cnt, __popc(m));
    base = __shfl_sync(0xFFFFFFFFu, base, leader);
    if (p) {
        int slot = base + __popc(m & ((1u << lane) - 1));
        if (slot < CAND) buf[slot] = key;
    }
}

__global__ void k_cls(const float* __restrict__ rpos, const float* __restrict__ rneg) {
    const int b = blockIdx.y;
    const int a = blockIdx.x * blockDim.x + threadIdx.x;
    const int i = b * A_N + a;

    __shared__ unsigned sba[T_N];
    __shared__ int sc[2];
    if (threadIdx.x < T_N)
        sba[threadIdx.x] = 0xFFFFFFFFu - (unsigned)(g_gt_best[b * T_N + threadIdx.x] & 0xFFFFFFFFull);
    if (threadIdx.x < 2) sc[threadIdx.x] = 0;
    __syncthreads();

    float im = g_iou_max[i];
    bool isb = false;
    #pragma unroll
    for (int g = 0; g < T_N; ++g) isb |= (sba[g] == (unsigned)a);
    int cls = -1;
    if (im < 0.3f) cls = 0;
    if (isb || im >= 0.7f) cls = 1;
    g_cls0[i] = (signed char)cls;

    const bool pos = (cls == 1);
    const bool neg = (cls == 0);

    unsigned mp = __ballot_sync(0xFFFFFFFFu, pos);
    unsigned mn = __ballot_sync(0xFFFFFFFFu, neg);
    if ((threadIdx.x & 31) == 0) {
        if (mp) atomicAdd(&sc[0], __popc(mp));
        if (mn) atomicAdd(&sc[1], __popc(mn));
    }

    float rp = pos ? rpos[i] : 0.f;
    push_cand(g_cand + (b * 2 + 0) * CAND, &g_ccnt[b * 2 + 0],
              ((ull)__float_as_uint(rp) << 32) | (unsigned)a, pos);
    float rn = neg ? rneg[i] : 1.f;
    push_cand(g_cand + (b * 2 + 1) * CAND, &g_ccnt[b * 2 + 1],
              ((ull)__float_as_uint(rn) << 32) | (unsigned)a, neg && (rn < NEG_TCUT));

    __syncthreads();
    if (threadIdx.x < 2 && sc[threadIdx.x]) atomicAdd(&g_tot[b * 2 + threadIdx.x], sc[threadIdx.x]);
}

__global__ void k_pick() {
    const int b = blockIdx.x;
    const int tid = threadIdx.x;
    __shared__ ull sk[CAND];

    const int P  = g_tot[b * 2 + 0];
    const int cp = g_ccnt[b * 2 + 0];
    const int Nn = g_tot[b * 2 + 1];
    const int cn = g_ccnt[b * 2 + 1];
    const int npos = (P < 128) ? P : 128;
    const int Kn = 256 - npos;

    if (P <= 128) {
        if (tid == 0) g_thresh[b * 2 + 0] = ~0ull;
    } else if (cp <= CAND) {
        for (int i = tid; i < cp; i += blockDim.x) sk[i] = g_cand[(b * 2 + 0) * CAND + i];
        __syncthreads();
        for (int i = tid; i < cp; i += blockDim.x) {
            ull me = sk[i];
            int c = 0;
            for (int j = 0; j < cp; ++j) c += (sk[j] < me);
            if (c == 127) g_thresh[b * 2 + 0] = me;
        }
        __syncthreads();
    } else {
        if (tid == 0) g_fb[b * 2 + 0] = 128;
    }

    if (Nn <= Kn) {
        if (tid == 0) g_thresh[b * 2 + 1] = ~0ull;
    } else if (cn >= Kn && cn <= CAND) {
        __syncthreads();
        for (int i = tid; i < cn; i += blockDim.x) sk[i] = g_cand[(b * 2 + 1) * CAND + i];
        __syncthreads();
        for (int i = tid; i < cn; i += blockDim.x) {
            ull me = sk[i];
            int c = 0;
            for (int j = 0; j < cn; ++j) c += (sk[j] < me);
            if (c == Kn - 1) g_thresh[b * 2 + 1] = me;
        }
    } else {
        if (tid == 0) g_fb[b * 2 + 1] = Kn;
    }
}

// ---- fallback exact radix select (normally early-exits) ----
__device__ __forceinline__ ull radix_select(const float* __restrict__ r,
                                            const signed char* __restrict__ cls,
                                            int want, int k, int* hist, int* sh) {
    ull prefix = 0;
    const int tid = threadIdx.x;
    for (int byte = 7; byte >= 0; --byte) {
        const int shift = byte * 8;
        if (tid < 256) hist[tid] = 0;
        __syncthreads();
        for (int i = tid; i < A_N; i += blockDim.x) {
            if (cls[i] == want) {
                ull key = ((ull)__float_as_uint(r[i]) << 32) | (unsigned)i;
                bool match = (byte == 7) || ((key >> (shift + 8)) == (prefix >> (shift + 8)));
                if (match) atomicAdd(&hist[(int)((key >> shift) & 0xFF)], 1);
            }
        }
        __syncthreads();
        if (tid == 0) {
            int cum = 0, d = 0;
            for (; d < 255; ++d) {
                if (cum + hist[d] >= k) break;
                cum += hist[d];
            }
            sh[0] = d;
            sh[1] = k - cum;
        }
        __syncthreads();
        prefix |= ((ull)sh[0]) << shift;
        k = sh[1];
        __syncthreads();
    }
    return prefix;
}

__global__ void k_fallback(const float* __restrict__ rpos, const float* __restrict__ rneg) {
    const int b = blockIdx.x;
    const int kp = g_fb[b * 2 + 0];
    const int kn = g_fb[b * 2 + 1];
    if (!(kp | kn)) return;
    __shared__ int hist[256];
    __shared__ int sh[2];
    if (kp) {
        ull t = radix_select(rpos + b * A_N, g_cls0 + b * A_N, 1, kp, hist, sh);
        if (threadIdx.x == 0) g_thresh[b * 2 + 0] = t;
    }
    if (kn) {
        ull t = radix_select(rneg + b * A_N, g_cls0 + b * A_N, 0, kn, hist, sh);
        if (threadIdx.x == 0) g_thresh[b * 2 + 1] = t;
    }
}

__global__ void k_out(const float4* __restrict__ anchors, const float4* __restrict__ gts,
                      const float* __restrict__ rpos, const float* __restrict__ rneg,
                      float* __restrict__ out) {
    const int b = blockIdx.y;
    const int a = blockIdx.x * blockDim.x + threadIdx.x;
    const int i = b * A_N + a;

    int cls = g_cls0[i];
    if (cls == 1) {
        ull key = ((ull)__float_as_uint(rpos[i]) << 32) | (unsigned)a;
        if (key > g_thresh[b * 2]) cls = -1;
    } else if (cls == 0) {
        ull key = ((ull)__float_as_uint(rneg[i]) << 32) | (unsigned)a;
        if (key > g_thresh[b * 2 + 1]) cls = -1;
    }
    out[i] = (float)cls;

    float4 d = make_float4(0.f, 0.f, 0.f, 0.f);
    if (cls == 1) {
        float4 box = anchors[i];
        bool inb = (box.x >= 0.f) && (box.y >= 0.f) && (box.z <= 1.f) && (box.w <= 1.f);
        if (!inb) { box.x = box.y = box.z = box.w = 0.f; }
        float4 gt = gts[b * T_N + g_best_g[i]];
        float ah = box.z - box.x, aw = box.w - box.y;
        float acy = box.x + 0.5f * ah, acx = box.y + 0.5f * aw;
        float gh = gt.z - gt.x, gw = gt.w - gt.y;
        float gcy = gt.x + 0.5f * gh, gcx = gt.y + 0.5f * gw;
        float ahs = (ah > 0.f) ? ah : 1.f;
        float aws = (aw > 0.f) ? aw : 1.f;
        float ghs = (gh > 0.f) ? gh : 1.f;
        float gws = (gw > 0.f) ? gw : 1.f;
        d.x = __fdiv_rn(gcy - acy, ahs);
        d.y = __fdiv_rn(gcx - acx, aws);
        d.z = logf(__fdiv_rn(ghs, ahs));
        d.w = logf(__fdiv_rn(gws, aws));
    }
    reinterpret_cast<float4*>(out + (size_t)N_B * A_N)[i] = d;
}

extern "C" void kernel_launch(void* const* d_in, const int* in_sizes, int n_in,
                              void* d_out, int out_size) {
    const float4* anchors = (const float4*)d_in[0];
    const float4* gts     = (const float4*)d_in[1];
    const float*  rp      = (const float*)d_in[2];
    const float*  rn      = (const float*)d_in[3];
    float* out = (float*)d_out;

    k_init<<<1, 512>>>();
    k_iou<<<dim3(A_N / APB, N_B), TPB>>>(anchors, gts);
    k_cls<<<dim3(A_N / 256, N_B), 256>>>(rp, rn);
    k_pick<<<N_B, 1024>>>();
    k_fallback<<<N_B, 1024>>>(rp, rn);
    k_out<<<dim3(A_N / 256, N_B), 256>>>(anchors, gts, rp, rn, out);
}

// round 5
// speedup vs baseline: 1.1135x; 1.0386x over previous
#include <cuda_runtime.h>

#define N_B 8
#define A_N 131072
#define T_N 64
#define CAND 4096
#define NEG_TCUT 0.004f
#define APT 8
#define TPB 256
#define APB (APT * TPB)
#define ONE_P 1.00001f
#define ONE_M 0.99999f
typedef unsigned long long ull;

__device__ ull           g_gt_best[N_B * T_N];
__device__ float         g_iou_max[N_B * A_N];
__device__ unsigned char g_best_g [N_B * A_N];
__device__ signed char   g_cls0  [N_B * A_N];
__device__ ull           g_thresh[N_B * 2];
__device__ int           g_tot   [N_B * 2];
__device__ int           g_ccnt  [N_B * 2];
__device__ ull           g_cand  [N_B * 2 * CAND];
__device__ int           g_fb    [N_B * 2];

__global__ void k_init() {
    const int i = threadIdx.x;
    if (i < N_B * T_N) g_gt_best[i] = 0xFFFFFFFFull;
    if (i < N_B * 2) { g_tot[i] = 0; g_ccnt[i] = 0; g_fb[i] = 0; }
}

__global__ __launch_bounds__(TPB) void k_iou(const float4* __restrict__ anchors,
                                             const float4* __restrict__ gts) {
    const int b   = blockIdx.y;
    const int tid = threadIdx.x;
    const int a0  = blockIdx.x * APB + tid;

    __shared__ float4 sgt [T_N];
    __shared__ float  sga [T_N];
    __shared__ ull    skey[T_N];

    if (tid < T_N) {
        float4 g = gts[b * T_N + tid];
        sgt[tid] = g;
        sga[tid] = (g.z - g.x) * (g.w - g.y);
        skey[tid] = 0ull;
    }
    __syncthreads();

    float4 box[APT];
    float  aarea[APT];
    float  bi[APT], bu[APT];          // row best as exact (inter, union) pair
    int    bg[APT];
    #pragma unroll
    for (int k = 0; k < APT; ++k) {
        float4 x = anchors[b * A_N + a0 + k * TPB];
        bool inb = (x.x >= 0.f) && (x.y >= 0.f) && (x.z <= 1.f) && (x.w <= 1.f);
        if (!inb) { x.x = x.y = x.z = x.w = 0.f; }
        box[k]   = x;
        aarea[k] = (x.z - x.x) * (x.w - x.y);
        bi[k] = 0.f; bu[k] = 1.f; bg[k] = 0;
    }

    #pragma unroll 1
    for (int g = 0; g < T_N; ++g) {
        const float4 G  = sgt[g];
        const float  ga = sga[g];
        float ci = 0.f, cu = 1.f;      // column (per-gt) winner in this thread
        unsigned ca = 0u;

        #pragma unroll
        for (int k = 0; k < APT; ++k) {
            float ih = fmaxf(fminf(box[k].z, G.z) - fmaxf(box[k].x, G.x), 0.f);
            float iw = fmaxf(fminf(box[k].w, G.w) - fmaxf(box[k].y, G.y), 0.f);
            float inter = ih * iw;
            float un = (aarea[k] + ga) - inter;   // > 0 whenever inter > 0

            // row update: switch iff fl(inter/un) > fl(bi/bu); ties keep earlier g
            float d1 = inter * bu[k], d2 = bi[k] * un;
            bool sw = d1 > d2 * ONE_P;
            if (!sw && d1 > d2 * ONE_M) {          // rare ambiguity -> exact fp32 compare
                float qn = __fdiv_rn(inter, un);
                float qo = (bi[k] > 0.f) ? __fdiv_rn(bi[k], bu[k]) : 0.f;
                sw = qn > qo;
            }
            if (sw) { bi[k] = inter; bu[k] = un; bg[k] = g; }

            // column update: strictly-greater keeps smallest anchor (k ascending)
            float e1 = inter * cu, e2 = ci * un;
            bool swc = e1 > e2 * ONE_P;
            if (!swc && e1 > e2 * ONE_M) {
                float qn = __fdiv_rn(inter, un);
                float qo = (ci > 0.f) ? __fdiv_rn(ci, cu) : 0.f;
                swc = qn > qo;
            }
            if (swc) { ci = inter; cu = un; ca = (unsigned)(a0 + k * TPB); }
        }

        // warp reduce column winner (max fl-iou, smallest anchor on fl-ties)
        #pragma unroll
        for (int off = 16; off >= 1; off >>= 1) {
            float    oi = __shfl_down_sync(0xFFFFFFFFu, ci, off);
            float    ou = __shfl_down_sync(0xFFFFFFFFu, cu, off);
            unsigned oa = __shfl_down_sync(0xFFFFFFFFu, ca, off);
            float e1 = oi * cu, e2 = ci * ou;
            bool take = e1 > e2 * ONE_P;
            if (!take && e1 > e2 * ONE_M) {
                float qn = (oi > 0.f) ? __fdiv_rn(oi, ou) : 0.f;
                float qo = (ci > 0.f) ? __fdiv_rn(ci, cu) : 0.f;
                take = (qn > qo) || (qn == qo && oa < ca);
            }
            if (take) { ci = oi; cu = ou; ca = oa; }
        }
        if ((tid & 31) == 0 && ci > 0.f) {
            float q = __fdiv_rn(ci, cu);           // one exact divide per warp per gt
            ull key = ((ull)__float_as_uint(q) << 32) | (0xFFFFFFFFu - ca);
            if (key > skey[g]) atomicMax(&skey[g], key);
        }
    }

    #pragma unroll
    for (int k = 0; k < APT; ++k) {
        float q = (bi[k] > 0.f) ? __fdiv_rn(bi[k], bu[k]) : 0.f;  // one per anchor
        g_iou_max[b * A_N + a0 + k * TPB] = q;
        g_best_g [b * A_N + a0 + k * TPB] = (unsigned char)bg[k];
    }

    __syncthreads();
    if (tid < T_N && skey[tid] > 0xFFFFFFFFull)
        atomicMax(&g_gt_best[b * T_N + tid], skey[tid]);
}

__device__ __forceinline__ void push_cand(ull* __restrict__ buf, int* __restrict__ cnt,
                                          ull key, bool p) {
    unsigned m = __ballot_sync(0xFFFFFFFFu, p);
    if (!m) return;
    int lane = threadIdx.x & 31;
    int leader = __ffs(m) - 1;
    int base = 0;
    if (lane == leader) base = atomicAdd(cnt, __popc(m));
    base = __shfl_sync(0xFFFFFFFFu, base, leader);
    if (p) {
        int slot = base + __popc(m & ((1u << lane) - 1));
        if (slot < CAND) buf[slot] = key;
    }
}

__global__ void k_cls(const float* __restrict__ rpos, const float* __restrict__ rneg) {
    const int b = blockIdx.y;
    const int a = blockIdx.x * blockDim.x + threadIdx.x;
    const int i = b * A_N + a;

    __shared__ unsigned sba[T_N];
    __shared__ int sc[2];
    if (threadIdx.x < T_N)
        sba[threadIdx.x] = 0xFFFFFFFFu - (unsigned)(g_gt_best[b * T_N + threadIdx.x] & 0xFFFFFFFFull);
    if (threadIdx.x < 2) sc[threadIdx.x] = 0;
    __syncthreads();

    float im = g_iou_max[i];
    bool isb = false;
    #pragma unroll
    for (int g = 0; g < T_N; ++g) isb |= (sba[g] == (unsigned)a);
    int cls = -1;
    if (im < 0.3f) cls = 0;
    if (isb || im >= 0.7f) cls = 1;
    g_cls0[i] = (signed char)cls;

    const bool pos = (cls == 1);
    const bool neg = (cls == 0);

    unsigned mp = __ballot_sync(0xFFFFFFFFu, pos);
    unsigned mn = __ballot_sync(0xFFFFFFFFu, neg);
    if ((threadIdx.x & 31) == 0) {
        if (mp) atomicAdd(&sc[0], __popc(mp));
        if (mn) atomicAdd(&sc[1], __popc(mn));
    }

    float rp = pos ? rpos[i] : 0.f;
    push_cand(g_cand + (b * 2 + 0) * CAND, &g_ccnt[b * 2 + 0],
              ((ull)__float_as_uint(rp) << 32) | (unsigned)a, pos);
    float rn = neg ? rneg[i] : 1.f;
    push_cand(g_cand + (b * 2 + 1) * CAND, &g_ccnt[b * 2 + 1],
              ((ull)__float_as_uint(rn) << 32) | (unsigned)a, neg && (rn < NEG_TCUT));

    __syncthreads();
    if (threadIdx.x < 2 && sc[threadIdx.x]) atomicAdd(&g_tot[b * 2 + threadIdx.x], sc[threadIdx.x]);
}

__global__ void k_pick() {
    const int b = blockIdx.x;
    const int tid = threadIdx.x;
    __shared__ ull sk[CAND];

    const int P  = g_tot[b * 2 + 0];
    const int cp = g_ccnt[b * 2 + 0];
    const int Nn = g_tot[b * 2 + 1];
    const int cn = g_ccnt[b * 2 + 1];
    const int npos = (P < 128) ? P : 128;
    const int Kn = 256 - npos;

    if (P <= 128) {
        if (tid == 0) g_thresh[b * 2 + 0] = ~0ull;
    } else if (cp <= CAND) {
        for (int i = tid; i < cp; i += blockDim.x) sk[i] = g_cand[(b * 2 + 0) * CAND + i];
        __syncthreads();
        for (int i = tid; i < cp; i += blockDim.x) {
            ull me = sk[i];
            int c = 0;
            for (int j = 0; j < cp; ++j) c += (sk[j] < me);
            if (c == 127) g_thresh[b * 2 + 0] = me;
        }
        __syncthreads();
    } else {
        if (tid == 0) g_fb[b * 2 + 0] = 128;
    }

    if (Nn <= Kn) {
        if (tid == 0) g_thresh[b * 2 + 1] = ~0ull;
    } else if (cn >= Kn && cn <= CAND) {
        __syncthreads();
        for (int i = tid; i < cn; i += blockDim.x) sk[i] = g_cand[(b * 2 + 1) * CAND + i];
        __syncthreads();
        for (int i = tid; i < cn; i += blockDim.x) {
            ull me = sk[i];
            int c = 0;
            for (int j = 0; j < cn; ++j) c += (sk[j] < me);
            if (c == Kn - 1) g_thresh[b * 2 + 1] = me;
        }
    } else {
        if (tid == 0) g_fb[b * 2 + 1] = Kn;
    }
}

__device__ __forceinline__ ull radix_select(const float* __restrict__ r,
                                            const signed char* __restrict__ cls,
                                            int want, int k, int* hist, int* sh) {
    ull prefix = 0;
    const int tid = threadIdx.x;
    for (int byte = 7; byte >= 0; --byte) {
        const int shift = byte * 8;
        if (tid < 256) hist[tid] = 0;
        __syncthreads();
        for (int i = tid; i < A_N; i += blockDim.x) {
            if (cls[i] == want) {
                ull key = ((ull)__float_as_uint(r[i]) << 32) | (unsigned)i;
                bool match = (byte == 7) || ((key >> (shift + 8)) == (prefix >> (shift + 8)));
                if (match) atomicAdd(&hist[(int)((key >> shift) & 0xFF)], 1);
            }
        }
        __syncthreads();
        if (tid == 0) {
            int cum = 0, d = 0;
            for (; d < 255; ++d) {
                if (cum + hist[d] >= k) break;
                cum += hist[d];
            }
            sh[0] = d;
            sh[1] = k - cum;
        }
        __syncthreads();
        prefix |= ((ull)sh[0]) << shift;
        k = sh[1];
        __syncthreads();
    }
    return prefix;
}

__global__ void k_fallback(const float* __restrict__ rpos, const float* __restrict__ rneg) {
    const int b = blockIdx.x;
    const int kp = g_fb[b * 2 + 0];
    const int kn = g_fb[b * 2 + 1];
    if (!(kp | kn)) return;
    __shared__ int hist[256];
    __shared__ int sh[2];
    if (kp) {
        ull t = radix_select(rpos + b * A_N, g_cls0 + b * A_N, 1, kp, hist, sh);
        if (threadIdx.x == 0) g_thresh[b * 2 + 0] = t;
    }
    if (kn) {
        ull t = radix_select(rneg + b * A_N, g_cls0 + b * A_N, 0, kn, hist, sh);
        if (threadIdx.x == 0) g_thresh[b * 2 + 1] = t;
    }
}

__global__ void k_out(const float4* __restrict__ anchors, const float4* __restrict__ gts,
                      const float* __restrict__ rpos, const float* __restrict__ rneg,
                      float* __restrict__ out) {
    const int b = blockIdx.y;
    const int a = blockIdx.x * blockDim.x + threadIdx.x;
    const int i = b * A_N + a;

    int cls = g_cls0[i];
    if (cls == 1) {
        ull key = ((ull)__float_as_uint(rpos[i]) << 32) | (unsigned)a;
        if (key > g_thresh[b * 2]) cls = -1;
    } else if (cls == 0) {
        ull key = ((ull)__float_as_uint(rneg[i]) << 32) | (unsigned)a;
        if (key > g_thresh[b * 2 + 1]) cls = -1;
    }
    out[i] = (float)cls;

    float4 d = make_float4(0.f, 0.f, 0.f, 0.f);
    if (cls == 1) {
        float4 box = anchors[i];
        bool inb = (box.x >= 0.f) && (box.y >= 0.f) && (box.z <= 1.f) && (box.w <= 1.f);
        if (!inb) { box.x = box.y = box.z = box.w = 0.f; }
        float4 gt = gts[b * T_N + g_best_g[i]];
        float ah = box.z - box.x, aw = box.w - box.y;
        float acy = box.x + 0.5f * ah, acx = box.y + 0.5f * aw;
        float gh = gt.z - gt.x, gw = gt.w - gt.y;
        float gcy = gt.x + 0.5f * gh, gcx = gt.y + 0.5f * gw;
        float ahs = (ah > 0.f) ? ah : 1.f;
        float aws = (aw > 0.f) ? aw : 1.f;
        float ghs = (gh > 0.f) ? gh : 1.f;
        float gws = (gw > 0.f) ? gw : 1.f;
        d.x = __fdiv_rn(gcy - acy, ahs);
        d.y = __fdiv_rn(gcx - acx, aws);
        d.z = logf(__fdiv_rn(ghs, ahs));
        d.w = logf(__fdiv_rn(gws, aws));
    }
    reinterpret_cast<float4*>(out + (size_t)N_B * A_N)[i] = d;
}

extern "C" void kernel_launch(void* const* d_in, const int* in_sizes, int n_in,
                              void* d_out, int out_size) {
    const float4* anchors = (const float4*)d_in[0];
    const float4* gts     = (const float4*)d_in[1];
    const float*  rp      = (const float*)d_in[2];
    const float*  rn      = (const float*)d_in[3];
    float* out = (float*)d_out;

    k_init<<<1, 512>>>();
    k_iou<<<dim3(A_N / APB, N_B), TPB>>>(anchors, gts);
    k_cls<<<dim3(A_N / 256, N_B), 256>>>(rp, rn);
    k_pick<<<N_B, 1024>>>();
    k_fallback<<<N_B, 1024>>>(rp, rn);
    k_out<<<dim3(A_N / 256, N_B), 256>>>(anchors, gts, rp, rn, out);
}

// round 6
// speedup vs baseline: 1.4413x; 1.2944x over previous
#include <cuda_runtime.h>

#define N_B 8
#define A_N 131072
#define T_N 64
#define CAND 4096
#define NEG_TCUT 0.004f
#define APT 4
#define TPB 256
#define APB (APT * TPB)       // 1024 anchors per block
#define ONE_P 1.00001f
#define ONE_M 0.99999f
typedef unsigned long long ull;

__device__ ull           g_gt_best[N_B * T_N];
__device__ float         g_iou_max[N_B * A_N];
__device__ unsigned char g_best_g [N_B * A_N];
__device__ signed char   g_cls0  [N_B * A_N];
__device__ ull           g_thresh[N_B * 2];
__device__ int           g_tot   [N_B * 2];
__device__ int           g_ccnt  [N_B * 2];
__device__ ull           g_cand  [N_B * 2 * CAND];
__device__ int           g_fb    [N_B * 2];

__global__ void k_init() {
    const int i = threadIdx.x;
    if (i < N_B * T_N) g_gt_best[i] = 0xFFFFFFFFull;
    if (i < N_B * 2) { g_tot[i] = 0; g_ccnt[i] = 0; g_fb[i] = 0; }
}

// Rare exact fl32 comparison (forces a CALL, never predicated into hot loop).
__device__ __noinline__ bool iou_gt(float i1, float u1, float i2, float u2) {
    float q1 = (i1 > 0.f) ? __fdiv_rn(i1, u1) : 0.f;
    float q2 = (i2 > 0.f) ? __fdiv_rn(i2, u2) : 0.f;
    return q1 > q2;
}

__global__ __launch_bounds__(TPB) void k_iou(const float4* __restrict__ anchors,
                                             const float4* __restrict__ gts) {
    const int b   = blockIdx.y;
    const int tid = threadIdx.x;
    const int a0  = blockIdx.x * APB + tid;

    __shared__ float4   sgt [T_N];
    __shared__ float    sga [T_N];
    __shared__ unsigned sflt[T_N];   // running best fl(iou) bits for this block (filter)
    __shared__ ull      skey[T_N];   // packed (bits<<32 | ~anchor)

    if (tid < T_N) {
        float4 g = gts[b * T_N + tid];
        sgt[tid] = g;
        sga[tid] = (g.z - g.x) * (g.w - g.y);
        sflt[tid] = 0u;
        skey[tid] = 0ull;
    }
    __syncthreads();

    float4 box[APT];
    float  aarea[APT];
    float  bi[APT], bu[APT];          // row best as exact (inter, union) pair
    int    bg[APT];
    #pragma unroll
    for (int k = 0; k < APT; ++k) {
        float4 x = anchors[b * A_N + a0 + k * TPB];
        bool inb = (x.x >= 0.f) && (x.y >= 0.f) && (x.z <= 1.f) && (x.w <= 1.f);
        if (!inb) { x.x = x.y = x.z = x.w = 0.f; }
        box[k]   = x;
        aarea[k] = (x.z - x.x) * (x.w - x.y);
        bi[k] = 0.f; bu[k] = 1.f; bg[k] = 0;
    }

    #pragma unroll 1
    for (int g = 0; g < T_N; ++g) {
        const float4 G  = sgt[g];
        const float  ga = sga[g];
        // conservative column filter (stale read OK; slack covers rounding + fl-ties)
        const float cf = __uint_as_float(sflt[g]) * 0.9999995f;

        #pragma unroll
        for (int k = 0; k < APT; ++k) {
            float ih = fmaxf(fminf(box[k].z, G.z) - fmaxf(box[k].x, G.x), 0.f);
            float iw = fmaxf(fminf(box[k].w, G.w) - fmaxf(box[k].y, G.y), 0.f);
            float inter = ih * iw;
            float un = (aarea[k] + ga) - inter;   // > 0 whenever inter > 0

            // ---- row (per-anchor) argmax over g, exact fl semantics ----
            float d1 = inter * bu[k], d2 = bi[k] * un;
            bool sw = d1 > d2 * ONE_P;
            if (!sw && d1 > d2 * ONE_M)            // ~1e-4 rare -> exact resolve via CALL
                sw = iou_gt(inter, un, bi[k], bu[k]);
            if (sw) { bi[k] = inter; bu[k] = un; bg[k] = g; }

            // ---- column (per-gt) argmax over anchors: filtered record-break ----
            if (inter > cf * un) {                 // rare after warm-up (~ln(1024)/gt/block)
                float q = __fdiv_rn(inter, un);
                unsigned bits = __float_as_uint(q);
                atomicMax(&sflt[g], bits);
                ull key = ((ull)bits << 32) | (0xFFFFFFFFu - (unsigned)(a0 + k * TPB));
                atomicMax(&skey[g], key);
            }
        }
    }

    #pragma unroll
    for (int k = 0; k < APT; ++k) {
        float q = (bi[k] > 0.f) ? __fdiv_rn(bi[k], bu[k]) : 0.f;  // one divide per anchor
        g_iou_max[b * A_N + a0 + k * TPB] = q;
        g_best_g [b * A_N + a0 + k * TPB] = (unsigned char)bg[k];
    }

    __syncthreads();
    if (tid < T_N && skey[tid] > 0xFFFFFFFFull)
        atomicMax(&g_gt_best[b * T_N + tid], skey[tid]);
}

__device__ __forceinline__ void push_cand(ull* __restrict__ buf, int* __restrict__ cnt,
                                          ull key, bool p) {
    unsigned m = __ballot_sync(0xFFFFFFFFu, p);
    if (!m) return;
    int lane = threadIdx.x & 31;
    int leader = __ffs(m) - 1;
    int base = 0;
    if (lane == leader) base = atomicAdd(cnt, __popc(m));
    base = __shfl_sync(0xFFFFFFFFu, base, leader);
    if (p) {
        int slot = base + __popc(m & ((1u << lane) - 1));
        if (slot < CAND) buf[slot] = key;
    }
}

__global__ void k_cls(const float* __restrict__ rpos, const float* __restrict__ rneg) {
    const int b = blockIdx.y;
    const int a = blockIdx.x * blockDim.x + threadIdx.x;
    const int i = b * A_N + a;

    __shared__ unsigned sba[T_N];
    __shared__ int sc[2];
    if (threadIdx.x < T_N)
        sba[threadIdx.x] = 0xFFFFFFFFu - (unsigned)(g_gt_best[b * T_N + threadIdx.x] & 0xFFFFFFFFull);
    if (threadIdx.x < 2) sc[threadIdx.x] = 0;
    __syncthreads();

    float im = g_iou_max[i];
    bool isb = false;
    #pragma unroll
    for (int g = 0; g < T_N; ++g) isb |= (sba[g] == (unsigned)a);
    int cls = -1;
    if (im < 0.3f) cls = 0;
    if (isb || im >= 0.7f) cls = 1;
    g_cls0[i] = (signed char)cls;

    const bool pos = (cls == 1);
    const bool neg = (cls == 0);

    unsigned mp = __ballot_sync(0xFFFFFFFFu, pos);
    unsigned mn = __ballot_sync(0xFFFFFFFFu, neg);
    if ((threadIdx.x & 31) == 0) {
        if (mp) atomicAdd(&sc[0], __popc(mp));
        if (mn) atomicAdd(&sc[1], __popc(mn));
    }

    float rp = pos ? rpos[i] : 0.f;
    push_cand(g_cand + (b * 2 + 0) * CAND, &g_ccnt[b * 2 + 0],
              ((ull)__float_as_uint(rp) << 32) | (unsigned)a, pos);
    float rn = neg ? rneg[i] : 1.f;
    push_cand(g_cand + (b * 2 + 1) * CAND, &g_ccnt[b * 2 + 1],
              ((ull)__float_as_uint(rn) << 32) | (unsigned)a, neg && (rn < NEG_TCUT));

    __syncthreads();
    if (threadIdx.x < 2 && sc[threadIdx.x]) atomicAdd(&g_tot[b * 2 + threadIdx.x], sc[threadIdx.x]);
}

__global__ void k_pick() {
    const int b = blockIdx.x;
    const int tid = threadIdx.x;
    __shared__ ull sk[CAND];

    const int P  = g_tot[b * 2 + 0];
    const int cp = g_ccnt[b * 2 + 0];
    const int Nn = g_tot[b * 2 + 1];
    const int cn = g_ccnt[b * 2 + 1];
    const int npos = (P < 128) ? P : 128;
    const int Kn = 256 - npos;

    if (P <= 128) {
        if (tid == 0) g_thresh[b * 2 + 0] = ~0ull;
    } else if (cp <= CAND) {
        for (int i = tid; i < cp; i += blockDim.x) sk[i] = g_cand[(b * 2 + 0) * CAND + i];
        __syncthreads();
        for (int i = tid; i < cp; i += blockDim.x) {
            ull me = sk[i];
            int c = 0;
            for (int j = 0; j < cp; ++j) c += (sk[j] < me);
            if (c == 127) g_thresh[b * 2 + 0] = me;
        }
        __syncthreads();
    } else {
        if (tid == 0) g_fb[b * 2 + 0] = 128;
    }

    if (Nn <= Kn) {
        if (tid == 0) g_thresh[b * 2 + 1] = ~0ull;
    } else if (cn >= Kn && cn <= CAND) {
        __syncthreads();
        for (int i = tid; i < cn; i += blockDim.x) sk[i] = g_cand[(b * 2 + 1) * CAND + i];
        __syncthreads();
        for (int i = tid; i < cn; i += blockDim.x) {
            ull me = sk[i];
            int c = 0;
            for (int j = 0; j < cn; ++j) c += (sk[j] < me);
            if (c == Kn - 1) g_thresh[b * 2 + 1] = me;
        }
    } else {
        if (tid == 0) g_fb[b * 2 + 1] = Kn;
    }
}

__device__ __forceinline__ ull radix_select(const float* __restrict__ r,
                                            const signed char* __restrict__ cls,
                                            int want, int k, int* hist, int* sh) {
    ull prefix = 0;
    const int tid = threadIdx.x;
    for (int byte = 7; byte >= 0; --byte) {
        const int shift = byte * 8;
        if (tid < 256) hist[tid] = 0;
        __syncthreads();
        for (int i = tid; i < A_N; i += blockDim.x) {
            if (cls[i] == want) {
                ull key = ((ull)__float_as_uint(r[i]) << 32) | (unsigned)i;
                bool match = (byte == 7) || ((key >> (shift + 8)) == (prefix >> (shift + 8)));
                if (match) atomicAdd(&hist[(int)((key >> shift) & 0xFF)], 1);
            }
        }
        __syncthreads();
        if (tid == 0) {
            int cum = 0, d = 0;
            for (; d < 255; ++d) {
                if (cum + hist[d] >= k) break;
                cum += hist[d];
            }
            sh[0] = d;
            sh[1] = k - cum;
        }
        __syncthreads();
        prefix |= ((ull)sh[0]) << shift;
        k = sh[1];
        __syncthreads();
    }
    return prefix;
}

__global__ void k_fallback(const float* __restrict__ rpos, const float* __restrict__ rneg) {
    const int b = blockIdx.x;
    const int kp = g_fb[b * 2 + 0];
    const int kn = g_fb[b * 2 + 1];
    if (!(kp | kn)) return;
    __shared__ int hist[256];
    __shared__ int sh[2];
    if (kp) {
        ull t = radix_select(rpos + b * A_N, g_cls0 + b * A_N, 1, kp, hist, sh);
        if (threadIdx.x == 0) g_thresh[b * 2 + 0] = t;
    }
    if (kn) {
        ull t = radix_select(rneg + b * A_N, g_cls0 + b * A_N, 0, kn, hist, sh);
        if (threadIdx.x == 0) g_thresh[b * 2 + 1] = t;
    }
}

__global__ void k_out(const float4* __restrict__ anchors, const float4* __restrict__ gts,
                      const float* __restrict__ rpos, const float* __restrict__ rneg,
                      float* __restrict__ out) {
    const int b = blockIdx.y;
    const int a = blockIdx.x * blockDim.x + threadIdx.x;
    const int i = b * A_N + a;

    int cls = g_cls0[i];
    if (cls == 1) {
        ull key = ((ull)__float_as_uint(rpos[i]) << 32) | (unsigned)a;
        if (key > g_thresh[b * 2]) cls = -1;
    } else if (cls == 0) {
        ull key = ((ull)__float_as_uint(rneg[i]) << 32) | (unsigned)a;
        if (key > g_thresh[b * 2 + 1]) cls = -1;
    }
    out[i] = (float)cls;

    float4 d = make_float4(0.f, 0.f, 0.f, 0.f);
    if (cls == 1) {
        float4 box = anchors[i];
        bool inb = (box.x >= 0.f) && (box.y >= 0.f) && (box.z <= 1.f) && (box.w <= 1.f);
        if (!inb) { box.x = box.y = box.z = box.w = 0.f; }
        float4 gt = gts[b * T_N + g_best_g[i]];
        float ah = box.z - box.x, aw = box.w - box.y;
        float acy = box.x + 0.5f * ah, acx = box.y + 0.5f * aw;
        float gh = gt.z - gt.x, gw = gt.w - gt.y;
        float gcy = gt.x + 0.5f * gh, gcx = gt.y + 0.5f * gw;
        float ahs = (ah > 0.f) ? ah : 1.f;
        float aws = (aw > 0.f) ? aw : 1.f;
        float ghs = (gh > 0.f) ? gh : 1.f;
        float gws = (gw > 0.f) ? gw : 1.f;
        d.x = __fdiv_rn(gcy - acy, ahs);
        d.y = __fdiv_rn(gcx - acx, aws);
        d.z = logf(__fdiv_rn(ghs, ahs));
        d.w = logf(__fdiv_rn(gws, aws));
    }
    reinterpret_cast<float4*>(out + (size_t)N_B * A_N)[i] = d;
}

extern "C" void kernel_launch(void* const* d_in, const int* in_sizes, int n_in,
                              void* d_out, int out_size) {
    const float4* anchors = (const float4*)d_in[0];
    const float4* gts     = (const float4*)d_in[1];
    const float*  rp      = (const float*)d_in[2];
    const float*  rn      = (const float*)d_in[3];
    float* out = (float*)d_out;

    k_init<<<1, 512>>>();
    k_iou<<<dim3(A_N / APB, N_B), TPB>>>(anchors, gts);
    k_cls<<<dim3(A_N / 256, N_B), 256>>>(rp, rn);
    k_pick<<<N_B, 1024>>>();
    k_fallback<<<N_B, 1024>>>(rp, rn);
    k_out<<<dim3(A_N / 256, N_B), 256>>>(anchors, gts, rp, rn, out);
}